// round 13
// baseline (speedup 1.0000x reference)
#include <cuda_runtime.h>

#define NB 8
#define NC 32
#define NN 3136
#define NK 9

// scratch (device globals: no runtime allocation allowed)
__device__ __align__(16) float g_xnT[NB * NN * NC];       // normalized x, [b][n][c]  (3.2 MB)
__device__ __align__(16) float g_Y[NB * NK * NN * NC];    // Y[b][k][m][o] = W_k @ x[b][:,m] (28.9 MB)
__device__ int g_idx[NB * NN * NK];                       // top-9 neighbor indices

// XLA:GPU f32 divide = div.full.f32 (full-range, ~2ulp, NOT IEEE).
// CONFIRMED by R12: fingerprint dropped to the 1-flip class with this.
__device__ __forceinline__ float div_full(float a, float b) {
    float r;
    asm("div.full.f32 %0, %1, %2;" : "=f"(r) : "f"(a), "f"(b));
    return r;
}

// ---------------------------------------------------------------------------
// Kernel 1: normalize columns, write [b][n][c].
// XLA:GPU column-reduce emitter model (reduced axis C=32 tiled by 4):
//   p_j = sum_{i=0..7} mul/add( x[4i+j]^2 )   -- 4 strided partials, no FMA
//   ss  = (p0+p2) + (p1+p3)                   -- shfl.down tree (off 2, then 1)
//   nrm = fmax(sqrt.rn(ss), 1e-12)
//   xn  = div.full.f32(x, nrm)                -- XLA:GPU divide
// ---------------------------------------------------------------------------
__global__ void normalize_kernel(const float* __restrict__ x) {
    __shared__ float s[32][33];
    __shared__ float nrm[32];
    int b = blockIdx.y;
    int n0 = blockIdx.x * 32;
    int tx = threadIdx.x, ty = threadIdx.y;
    s[ty][tx] = x[(b * NC + ty) * NN + n0 + tx];
    __syncthreads();
    if (ty == 0) {
        float p0 = 0.f, p1 = 0.f, p2 = 0.f, p3 = 0.f;
#pragma unroll
        for (int i = 0; i < 8; i++) {
            float t0 = s[4 * i + 0][tx];
            float t1 = s[4 * i + 1][tx];
            float t2 = s[4 * i + 2][tx];
            float t3 = s[4 * i + 3][tx];
            p0 = __fadd_rn(p0, __fmul_rn(t0, t0));
            p1 = __fadd_rn(p1, __fmul_rn(t1, t1));
            p2 = __fadd_rn(p2, __fmul_rn(t2, t2));
            p3 = __fadd_rn(p3, __fmul_rn(t3, t3));
        }
        // shfl.down tree over 4 partials: offset 2, then offset 1
        float ss = __fadd_rn(__fadd_rn(p0, p2), __fadd_rn(p1, p3));
        nrm[tx] = fmaxf(__fsqrt_rn(ss), 1e-12f);
    }
    __syncthreads();
    g_xnT[(b * NN + n0 + ty) * NC + tx] = div_full(s[tx][ty], nrm[ty]);
}

// ---------------------------------------------------------------------------
// Kernel 2: fused cosine-sim GEMM (32 rows x 3136 cols per block) + top-9.
// Sequential ascending-c single-accumulator FFMA chain (cuBLAS sgemm K=32).
// ---------------------------------------------------------------------------
__global__ __launch_bounds__(256) void simtopk_kernel() {
    __shared__ __align__(16) float rowS[32 * 32];    // [c][r]
    __shared__ __align__(16) float colS[32 * 132];   // [c][m] (stride 132); reused as idx buf
    __shared__ __align__(16) float simS[32 * 132];   // [r][m] (stride 132); reused as val buf

    int b = blockIdx.y;
    int r0 = blockIdx.x * 32;
    int tid = threadIdx.x;
    const float4* xnT4 = reinterpret_cast<const float4*>(g_xnT);

    // load 32 row vectors, transpose to c-major
    {
        int r = tid >> 3, c4 = tid & 7;
        float4 v = xnT4[(b * NN + r0 + r) * 8 + c4];
        rowS[(4 * c4 + 0) * 32 + r] = v.x;
        rowS[(4 * c4 + 1) * 32 + r] = v.y;
        rowS[(4 * c4 + 2) * 32 + r] = v.z;
        rowS[(4 * c4 + 3) * 32 + r] = v.w;
    }

    float vals[9];
    int idxs[9];
#pragma unroll
    for (int k = 0; k < 9; k++) { vals[k] = -3.f; idxs[k] = 0x7fffffff; }

    int ty = tid >> 5, tx = tid & 31;   // GEMM: row-quad ty*4, col-quad tx*4
    int srow = tid >> 3, g = tid & 7;   // scan: 8 threads per row
    int rglob = r0 + srow;

    for (int t = 0; t < 25; t++) {
        int mbase = t * 128;
        __syncthreads();  // prior GEMM/scan done before colS overwrite
        // load 128 col vectors, transpose to c-major
#pragma unroll
        for (int i = 0; i < 4; i++) {
            int l = tid + i * 256;
            int m = l >> 3, c4 = l & 7;
            int gm = mbase + m;
            float4 v = make_float4(0.f, 0.f, 0.f, 0.f);
            if (gm < NN) v = xnT4[(b * NN + gm) * 8 + c4];
            colS[(4 * c4 + 0) * 132 + m] = v.x;
            colS[(4 * c4 + 1) * 132 + m] = v.y;
            colS[(4 * c4 + 2) * 132 + m] = v.z;
            colS[(4 * c4 + 3) * 132 + m] = v.w;
        }
        __syncthreads();

        float4 acc0 = {0, 0, 0, 0}, acc1 = {0, 0, 0, 0};
        float4 acc2 = {0, 0, 0, 0}, acc3 = {0, 0, 0, 0};
#pragma unroll
        for (int c = 0; c < 32; c++) {
            float4 a  = *reinterpret_cast<const float4*>(&rowS[c * 32 + ty * 4]);
            float4 bb = *reinterpret_cast<const float4*>(&colS[c * 132 + tx * 4]);
            acc0.x = __fmaf_rn(a.x, bb.x, acc0.x); acc0.y = __fmaf_rn(a.x, bb.y, acc0.y);
            acc0.z = __fmaf_rn(a.x, bb.z, acc0.z); acc0.w = __fmaf_rn(a.x, bb.w, acc0.w);
            acc1.x = __fmaf_rn(a.y, bb.x, acc1.x); acc1.y = __fmaf_rn(a.y, bb.y, acc1.y);
            acc1.z = __fmaf_rn(a.y, bb.z, acc1.z); acc1.w = __fmaf_rn(a.y, bb.w, acc1.w);
            acc2.x = __fmaf_rn(a.z, bb.x, acc2.x); acc2.y = __fmaf_rn(a.z, bb.y, acc2.y);
            acc2.z = __fmaf_rn(a.z, bb.z, acc2.z); acc2.w = __fmaf_rn(a.z, bb.w, acc2.w);
            acc3.x = __fmaf_rn(a.w, bb.x, acc3.x); acc3.y = __fmaf_rn(a.w, bb.y, acc3.y);
            acc3.z = __fmaf_rn(a.w, bb.z, acc3.z); acc3.w = __fmaf_rn(a.w, bb.w, acc3.w);
        }
        *reinterpret_cast<float4*>(&simS[(ty * 4 + 0) * 132 + tx * 4]) = acc0;
        *reinterpret_cast<float4*>(&simS[(ty * 4 + 1) * 132 + tx * 4]) = acc1;
        *reinterpret_cast<float4*>(&simS[(ty * 4 + 2) * 132 + tx * 4]) = acc2;
        *reinterpret_cast<float4*>(&simS[(ty * 4 + 3) * 132 + tx * 4]) = acc3;
        __syncthreads();

        // scan: 8 threads per row, interleaved cols, ascending m (stable ties)
#pragma unroll
        for (int j = 0; j < 16; j++) {
            int mm = g + j * 8;
            int gm = mbase + mm;
            if (gm < NN) {
                float v = simS[srow * 132 + mm];
                v = fminf(fmaxf(v, -1.f), 1.f);
                if (gm == rglob) v = 1.1f;   // self always best
                if (v > vals[8]) {
                    float cv = v; int ci = gm;
#pragma unroll
                    for (int s = 0; s < 9; s++) {
                        if (cv > vals[s]) {
                            float tv = vals[s]; int ti = idxs[s];
                            vals[s] = cv; idxs[s] = ci;
                            cv = tv; ci = ti;
                        }
                    }
                }
            }
        }
    }
    __syncthreads();

    // dump per-thread sorted top-9, then merge 8 lists per row (1 warp)
    int* colI = reinterpret_cast<int*>(colS);
    int base = (srow * 8 + g) * 9;
#pragma unroll
    for (int k = 0; k < 9; k++) { simS[base + k] = vals[k]; colI[base + k] = idxs[k]; }
    __syncthreads();

    if (tid < 32) {
        float* mv = &simS[tid * 72];
        int*   mi = &colI[tid * 72];
        int obase = (b * NN + r0 + tid) * 9;
        for (int k = 0; k < 9; k++) {
            float bv = -4.f; int bm = 0x7fffffff; int be = 0;
            for (int e = 0; e < 72; e++) {
                float v = mv[e];
                int m2 = mi[e];
                if (v > bv || (v == bv && m2 < bm)) { bv = v; bm = m2; be = e; }
            }
            mv[be] = -4.f;  // consume
            g_idx[obase + k] = bm;
        }
    }
}

// ---------------------------------------------------------------------------
// Kernel 3: dense GEMM  Y[b][k][m][o] = sum_c w[o][c][k] * x[b][c][m]
// ---------------------------------------------------------------------------
__global__ __launch_bounds__(256) void convA_kernel(const float* __restrict__ x,
                                                    const float* __restrict__ w) {
    __shared__ __align__(16) float wS[32 * 32];    // [c][o]
    __shared__ __align__(16) float xfS[32 * 132];  // [c][m]
    int mt = blockIdx.x, k = blockIdx.y, b = blockIdx.z;
    int mbase = mt * 128;
    int tid = threadIdx.x;

    for (int l = tid; l < 1024; l += 256) {
        int c = l >> 5, o = l & 31;
        wS[c * 32 + o] = w[o * (NC * NK) + c * NK + k];
    }
#pragma unroll
    for (int i = 0; i < 16; i++) {
        int l = tid + i * 256;
        int c = l >> 7, m = l & 127;
        int gm = mbase + m;
        xfS[c * 132 + m] = (gm < NN) ? x[(b * NC + c) * NN + gm] : 0.f;
    }
    __syncthreads();

    int ty = tid >> 5, tx = tid & 31;   // o-quad ty*4, m-quad tx*4
    float4 acc0 = {0, 0, 0, 0}, acc1 = {0, 0, 0, 0};
    float4 acc2 = {0, 0, 0, 0}, acc3 = {0, 0, 0, 0};
#pragma unroll
    for (int c = 0; c < 32; c++) {
        float4 of = *reinterpret_cast<const float4*>(&wS[c * 32 + ty * 4]);
        float4 mf = *reinterpret_cast<const float4*>(&xfS[c * 132 + tx * 4]);
        acc0.x = __fmaf_rn(of.x, mf.x, acc0.x); acc0.y = __fmaf_rn(of.y, mf.x, acc0.y);
        acc0.z = __fmaf_rn(of.z, mf.x, acc0.z); acc0.w = __fmaf_rn(of.w, mf.x, acc0.w);
        acc1.x = __fmaf_rn(of.x, mf.y, acc1.x); acc1.y = __fmaf_rn(of.y, mf.y, acc1.y);
        acc1.z = __fmaf_rn(of.z, mf.y, acc1.z); acc1.w = __fmaf_rn(of.w, mf.y, acc1.w);
        acc2.x = __fmaf_rn(of.x, mf.z, acc2.x); acc2.y = __fmaf_rn(of.y, mf.z, acc2.y);
        acc2.z = __fmaf_rn(of.z, mf.z, acc2.z); acc2.w = __fmaf_rn(of.w, mf.z, acc2.w);
        acc3.x = __fmaf_rn(of.x, mf.w, acc3.x); acc3.y = __fmaf_rn(of.y, mf.w, acc3.y);
        acc3.z = __fmaf_rn(of.z, mf.w, acc3.z); acc3.w = __fmaf_rn(of.w, mf.w, acc3.w);
    }
    int ybase = (b * NK + k) * NN;
    float4 acc[4] = {acc0, acc1, acc2, acc3};
#pragma unroll
    for (int j = 0; j < 4; j++) {
        int gm = mbase + tx * 4 + j;
        if (gm < NN)
            *reinterpret_cast<float4*>(&g_Y[(ybase + gm) * 32 + ty * 4]) = acc[j];
    }
}

// ---------------------------------------------------------------------------
// Kernel 4: gather-sum  out[b][o][n] = bias[o] + sum_k Y[b][k][idx[n][k]][o]
// ---------------------------------------------------------------------------
__global__ __launch_bounds__(256) void gather_kernel(const float* __restrict__ bias,
                                                     float* __restrict__ out) {
    int tid = threadIdx.x;
    int lane = tid & 31;
    int wg = blockIdx.x * 8 + (tid >> 5);   // one warp per (b, n)
    int b = wg / NN, n = wg - b * NN;
    int myidx = 0;
    if (lane < NK) myidx = g_idx[(b * NN + n) * NK + lane];
    float acc = bias[lane];
#pragma unroll
    for (int k = 0; k < NK; k++) {
        int m = __shfl_sync(0xffffffffu, myidx, k);
        acc += g_Y[((b * NK + k) * NN + m) * 32 + lane];  // 128B coalesced
    }
    out[(b * NC + lane) * NN + n] = acc;
}

// ---------------------------------------------------------------------------
extern "C" void kernel_launch(void* const* d_in, const int* in_sizes, int n_in,
                              void* d_out, int out_size) {
    const float* x    = (const float*)d_in[0];
    const float* w    = (const float*)d_in[1];
    const float* bias = (const float*)d_in[2];
    float* out = (float*)d_out;
    (void)in_sizes; (void)n_in; (void)out_size;

    normalize_kernel<<<dim3(NN / 32, NB), dim3(32, 32)>>>(x);
    simtopk_kernel<<<dim3(NN / 32, NB), 256>>>();
    convA_kernel<<<dim3(25, NK, NB), 256>>>(x, w);
    gather_kernel<<<NB * NN / 8, 256>>>(bias, out);
}

// round 14
// speedup vs baseline: 1.1354x; 1.1354x over previous
#include <cuda_runtime.h>

#define NB 8
#define NC 32
#define NN 3136
#define NK 9

// scratch (device globals: no runtime allocation allowed)
__device__ __align__(16) float g_xnT[NB * NN * NC];       // normalized x, [b][n][c]  (3.2 MB)
__device__ __align__(16) float g_Y[NB * NK * NN * NC];    // Y[b][k][m][o] = W_k @ x[b][:,m] (28.9 MB)
__device__ int g_idx[NB * NN * NK];                       // top-9 neighbor indices

// XLA:GPU f32 divide = div.full.f32 (CONFIRMED R13 — do not change)
__device__ __forceinline__ float div_full(float a, float b) {
    float r;
    asm("div.full.f32 %0, %1, %2;" : "=f"(r) : "f"(a), "f"(b));
    return r;
}

// Packed dual-fp32 FMA: each component is an independent correctly-rounded
// fp32 FMA -> bit-identical to scalar FFMA chains, 2x issue density.
__device__ __forceinline__ unsigned long long ffma2(unsigned long long a,
                                                    unsigned long long b,
                                                    unsigned long long c) {
    unsigned long long d;
    asm("fma.rn.f32x2 %0, %1, %2, %3;" : "=l"(d) : "l"(a), "l"(b), "l"(c));
    return d;
}
__device__ __forceinline__ unsigned long long pack2(float v) {
    unsigned long long d;
    asm("mov.b64 %0, {%1, %1};" : "=l"(d) : "f"(v));
    return d;
}

// ---------------------------------------------------------------------------
// Kernel 1: normalize columns -> [b][n][c]. FROZEN NUMERICS (R13 PASS):
// strided-4 mul/add partials, (p0+p2)+(p1+p3), sqrt.rn, max, div.full.
// ---------------------------------------------------------------------------
__global__ void normalize_kernel(const float* __restrict__ x) {
    __shared__ float s[32][33];
    __shared__ float nrm[32];
    int b = blockIdx.y;
    int n0 = blockIdx.x * 32;
    int tx = threadIdx.x, ty = threadIdx.y;
    s[ty][tx] = x[(b * NC + ty) * NN + n0 + tx];
    __syncthreads();
    if (ty == 0) {
        float p0 = 0.f, p1 = 0.f, p2 = 0.f, p3 = 0.f;
#pragma unroll
        for (int i = 0; i < 8; i++) {
            float t0 = s[4 * i + 0][tx];
            float t1 = s[4 * i + 1][tx];
            float t2 = s[4 * i + 2][tx];
            float t3 = s[4 * i + 3][tx];
            p0 = __fadd_rn(p0, __fmul_rn(t0, t0));
            p1 = __fadd_rn(p1, __fmul_rn(t1, t1));
            p2 = __fadd_rn(p2, __fmul_rn(t2, t2));
            p3 = __fadd_rn(p3, __fmul_rn(t3, t3));
        }
        float ss = __fadd_rn(__fadd_rn(p0, p2), __fadd_rn(p1, p3));
        nrm[tx] = fmaxf(__fsqrt_rn(ss), 1e-12f);
    }
    __syncthreads();
    g_xnT[(b * NN + n0 + ty) * NC + tx] = div_full(s[tx][ty], nrm[ty]);
}

// ---------------------------------------------------------------------------
// Kernel 2: fused cosine-sim GEMM + top-9.
// 64 rows x 3136 cols per block, col tiles of 128. 4 rows x 8 cols per
// thread via FFMA2 (col pairs packed). Per-output chain: ascending c,
// single accumulator, correctly-rounded FMA — IDENTICAL bits to R13.
// colS/simS share one buffer (written only after GEMM reads finish).
// ---------------------------------------------------------------------------
__global__ __launch_bounds__(256, 3) void simtopk_kernel() {
    __shared__ __align__(16) float rowS[32 * 64];    // [c][r], 8.2 KB
    __shared__ __align__(16) float buf[64 * 132];    // colS[c][m] / simS[r][m] / merge, 33.8 KB

    int b = blockIdx.y;
    int r0 = blockIdx.x * 64;
    int tid = threadIdx.x;
    const float4* xnT4 = reinterpret_cast<const float4*>(g_xnT);

    // load 64 row vectors, transpose to c-major [c][r]
#pragma unroll
    for (int i = 0; i < 2; i++) {
        int l = tid + i * 256;
        int r = l >> 3, c4 = l & 7;
        float4 v = xnT4[(b * NN + r0 + r) * 8 + c4];
        rowS[(4 * c4 + 0) * 64 + r] = v.x;
        rowS[(4 * c4 + 1) * 64 + r] = v.y;
        rowS[(4 * c4 + 2) * 64 + r] = v.z;
        rowS[(4 * c4 + 3) * 64 + r] = v.w;
    }

    float vals[9];
    int idxs[9];
#pragma unroll
    for (int k = 0; k < 9; k++) { vals[k] = -3.f; idxs[k] = 0x7fffffff; }

    int rq = tid >> 4, tx = tid & 15;   // GEMM: rows rq*4..+3, col quads tx*4 and 64+tx*4
    int srow = tid >> 2, g = tid & 3;   // scan: 4 threads per row
    int rglob = r0 + srow;

    for (int t = 0; t < 25; t++) {
        int mbase = t * 128;
        __syncthreads();  // prior scan done before buf overwrite (colS)
        // load 128 col vectors into buf as [c][m], stride 132
#pragma unroll
        for (int i = 0; i < 4; i++) {
            int l = tid + i * 256;
            int m = l >> 3, c4 = l & 7;
            int gm = mbase + m;
            float4 v = make_float4(0.f, 0.f, 0.f, 0.f);
            if (gm < NN) v = xnT4[(b * NN + gm) * 8 + c4];
            buf[(4 * c4 + 0) * 132 + m] = v.x;
            buf[(4 * c4 + 1) * 132 + m] = v.y;
            buf[(4 * c4 + 2) * 132 + m] = v.z;
            buf[(4 * c4 + 3) * 132 + m] = v.w;
        }
        __syncthreads();

        // acc[r][j]: r = row in quad, j = col-pair (0,1: quad tx*4; 2,3: quad 64+tx*4)
        unsigned long long acc[4][4];
#pragma unroll
        for (int r = 0; r < 4; r++)
#pragma unroll
            for (int j = 0; j < 4; j++) acc[r][j] = 0ull;

#pragma unroll
        for (int c = 0; c < 32; c++) {
            float4 rv = *reinterpret_cast<const float4*>(&rowS[c * 64 + rq * 4]);
            ulonglong2 cp1 = *reinterpret_cast<const ulonglong2*>(&buf[c * 132 + tx * 4]);
            ulonglong2 cp2 = *reinterpret_cast<const ulonglong2*>(&buf[c * 132 + 64 + tx * 4]);
            unsigned long long rr0 = pack2(rv.x), rr1 = pack2(rv.y);
            unsigned long long rr2 = pack2(rv.z), rr3 = pack2(rv.w);
            acc[0][0] = ffma2(rr0, cp1.x, acc[0][0]); acc[0][1] = ffma2(rr0, cp1.y, acc[0][1]);
            acc[0][2] = ffma2(rr0, cp2.x, acc[0][2]); acc[0][3] = ffma2(rr0, cp2.y, acc[0][3]);
            acc[1][0] = ffma2(rr1, cp1.x, acc[1][0]); acc[1][1] = ffma2(rr1, cp1.y, acc[1][1]);
            acc[1][2] = ffma2(rr1, cp2.x, acc[1][2]); acc[1][3] = ffma2(rr1, cp2.y, acc[1][3]);
            acc[2][0] = ffma2(rr2, cp1.x, acc[2][0]); acc[2][1] = ffma2(rr2, cp1.y, acc[2][1]);
            acc[2][2] = ffma2(rr2, cp2.x, acc[2][2]); acc[2][3] = ffma2(rr2, cp2.y, acc[2][3]);
            acc[3][0] = ffma2(rr3, cp1.x, acc[3][0]); acc[3][1] = ffma2(rr3, cp1.y, acc[3][1]);
            acc[3][2] = ffma2(rr3, cp2.x, acc[3][2]); acc[3][3] = ffma2(rr3, cp2.y, acc[3][3]);
        }
        __syncthreads();  // all GEMM reads of colS done before sim overwrite

        // write sim tile into buf as [r][m], stride 132 (packed pairs = in-order floats)
#pragma unroll
        for (int r = 0; r < 4; r++) {
            ulonglong2 q1; q1.x = acc[r][0]; q1.y = acc[r][1];
            ulonglong2 q2; q2.x = acc[r][2]; q2.y = acc[r][3];
            *reinterpret_cast<ulonglong2*>(&buf[(rq * 4 + r) * 132 + tx * 4]) = q1;
            *reinterpret_cast<ulonglong2*>(&buf[(rq * 4 + r) * 132 + 64 + tx * 4]) = q2;
        }
        __syncthreads();

        // scan: 4 threads per row, interleaved cols, ascending m (stable ties)
#pragma unroll
        for (int j = 0; j < 32; j++) {
            int mm = g + j * 4;
            int gm = mbase + mm;
            if (gm < NN) {
                float v = buf[srow * 132 + mm];
                v = fminf(fmaxf(v, -1.f), 1.f);
                if (gm == rglob) v = 1.1f;   // self always best
                if (v > vals[8]) {
                    float cv = v; int ci = gm;
#pragma unroll
                    for (int s = 0; s < 9; s++) {
                        if (cv > vals[s]) {
                            float tv = vals[s]; int ti = idxs[s];
                            vals[s] = cv; idxs[s] = ci;
                            cv = tv; ci = ti;
                        }
                    }
                }
            }
        }
    }
    __syncthreads();

    // dump per-thread sorted top-9 (vals in buf[0..2303], idxs at int offset 4224)
    int* bufI = reinterpret_cast<int*>(buf) + 4224;
    int base = (srow * 4 + g) * 9;
#pragma unroll
    for (int k = 0; k < 9; k++) { buf[base + k] = vals[k]; bufI[base + k] = idxs[k]; }
    __syncthreads();

    // merge 4 lists (36 entries) per row; one thread per row
    if (tid < 64) {
        float* mv = &buf[tid * 36];
        int*   mi = &bufI[tid * 36];
        int obase = (b * NN + r0 + tid) * 9;
        for (int k = 0; k < 9; k++) {
            float bv = -4.f; int bm = 0x7fffffff; int be = 0;
            for (int e = 0; e < 36; e++) {
                float v = mv[e];
                int m2 = mi[e];
                if (v > bv || (v == bv && m2 < bm)) { bv = v; bm = m2; be = e; }
            }
            mv[be] = -4.f;  // consume
            g_idx[obase + k] = bm;
        }
    }
}

// ---------------------------------------------------------------------------
// Kernel 3: dense GEMM  Y[b][k][m][o] = sum_c w[o][c][k] * x[b][c][m]
// ---------------------------------------------------------------------------
__global__ __launch_bounds__(256) void convA_kernel(const float* __restrict__ x,
                                                    const float* __restrict__ w) {
    __shared__ __align__(16) float wS[32 * 32];    // [c][o]
    __shared__ __align__(16) float xfS[32 * 132];  // [c][m]
    int mt = blockIdx.x, k = blockIdx.y, b = blockIdx.z;
    int mbase = mt * 128;
    int tid = threadIdx.x;

    for (int l = tid; l < 1024; l += 256) {
        int c = l >> 5, o = l & 31;
        wS[c * 32 + o] = w[o * (NC * NK) + c * NK + k];
    }
#pragma unroll
    for (int i = 0; i < 16; i++) {
        int l = tid + i * 256;
        int c = l >> 7, m = l & 127;
        int gm = mbase + m;
        xfS[c * 132 + m] = (gm < NN) ? x[(b * NC + c) * NN + gm] : 0.f;
    }
    __syncthreads();

    int ty = tid >> 5, tx = tid & 31;   // o-quad ty*4, m-quad tx*4
    float4 acc0 = {0, 0, 0, 0}, acc1 = {0, 0, 0, 0};
    float4 acc2 = {0, 0, 0, 0}, acc3 = {0, 0, 0, 0};
#pragma unroll
    for (int c = 0; c < 32; c++) {
        float4 of = *reinterpret_cast<const float4*>(&wS[c * 32 + ty * 4]);
        float4 mf = *reinterpret_cast<const float4*>(&xfS[c * 132 + tx * 4]);
        acc0.x = __fmaf_rn(of.x, mf.x, acc0.x); acc0.y = __fmaf_rn(of.y, mf.x, acc0.y);
        acc0.z = __fmaf_rn(of.z, mf.x, acc0.z); acc0.w = __fmaf_rn(of.w, mf.x, acc0.w);
        acc1.x = __fmaf_rn(of.x, mf.y, acc1.x); acc1.y = __fmaf_rn(of.y, mf.y, acc1.y);
        acc1.z = __fmaf_rn(of.z, mf.y, acc1.z); acc1.w = __fmaf_rn(of.w, mf.y, acc1.w);
        acc2.x = __fmaf_rn(of.x, mf.z, acc2.x); acc2.y = __fmaf_rn(of.y, mf.z, acc2.y);
        acc2.z = __fmaf_rn(of.z, mf.z, acc2.z); acc2.w = __fmaf_rn(of.w, mf.z, acc2.w);
        acc3.x = __fmaf_rn(of.x, mf.w, acc3.x); acc3.y = __fmaf_rn(of.y, mf.w, acc3.y);
        acc3.z = __fmaf_rn(of.z, mf.w, acc3.z); acc3.w = __fmaf_rn(of.w, mf.w, acc3.w);
    }
    int ybase = (b * NK + k) * NN;
    float4 acc[4] = {acc0, acc1, acc2, acc3};
#pragma unroll
    for (int j = 0; j < 4; j++) {
        int gm = mbase + tx * 4 + j;
        if (gm < NN)
            *reinterpret_cast<float4*>(&g_Y[(ybase + gm) * 32 + ty * 4]) = acc[j];
    }
}

// ---------------------------------------------------------------------------
// Kernel 4: gather-sum  out[b][o][n] = bias[o] + sum_k Y[b][k][idx[n][k]][o]
// ---------------------------------------------------------------------------
__global__ __launch_bounds__(256) void gather_kernel(const float* __restrict__ bias,
                                                     float* __restrict__ out) {
    int tid = threadIdx.x;
    int lane = tid & 31;
    int wg = blockIdx.x * 8 + (tid >> 5);   // one warp per (b, n)
    int b = wg / NN, n = wg - b * NN;
    int myidx = 0;
    if (lane < NK) myidx = g_idx[(b * NN + n) * NK + lane];
    float acc = bias[lane];
#pragma unroll
    for (int k = 0; k < NK; k++) {
        int m = __shfl_sync(0xffffffffu, myidx, k);
        acc += g_Y[((b * NK + k) * NN + m) * 32 + lane];  // 128B coalesced
    }
    out[(b * NC + lane) * NN + n] = acc;
}

// ---------------------------------------------------------------------------
extern "C" void kernel_launch(void* const* d_in, const int* in_sizes, int n_in,
                              void* d_out, int out_size) {
    const float* x    = (const float*)d_in[0];
    const float* w    = (const float*)d_in[1];
    const float* bias = (const float*)d_in[2];
    float* out = (float*)d_out;
    (void)in_sizes; (void)n_in; (void)out_size;

    normalize_kernel<<<dim3(NN / 32, NB), dim3(32, 32)>>>(x);
    simtopk_kernel<<<dim3(NN / 64, NB), 256>>>();
    convA_kernel<<<dim3(25, NK, NB), 256>>>(x, w);
    gather_kernel<<<NB * NN / 8, 256>>>(bias, out);
}

// round 15
// speedup vs baseline: 1.4047x; 1.2372x over previous
#include <cuda_runtime.h>

#define NB 8
#define NC 32
#define NN 3136
#define NK 9

// scratch (device globals: no runtime allocation allowed)
__device__ __align__(16) float g_xnT[NB * NN * NC];       // normalized x, [b][n][c]  (3.2 MB)
__device__ __align__(16) float g_Y[NB * NK * NN * NC];    // Y[b][k][m][o] (28.9 MB)
__device__ int g_idx[NB * NN * NK];                       // top-9 neighbor indices

// XLA:GPU f32 divide = div.full.f32 (CONFIRMED R13 — FROZEN)
__device__ __forceinline__ float div_full(float a, float b) {
    float r;
    asm("div.full.f32 %0, %1, %2;" : "=f"(r) : "f"(a), "f"(b));
    return r;
}

// Packed dual-fp32 FMA: per-lane correctly-rounded -> bit-identical chains.
__device__ __forceinline__ unsigned long long ffma2(unsigned long long a,
                                                    unsigned long long b,
                                                    unsigned long long c) {
    unsigned long long d;
    asm("fma.rn.f32x2 %0, %1, %2, %3;" : "=l"(d) : "l"(a), "l"(b), "l"(c));
    return d;
}
__device__ __forceinline__ unsigned long long pack2(float v) {
    unsigned long long d;
    asm("mov.b64 %0, {%1, %1};" : "=l"(d) : "f"(v));
    return d;
}

// ---------------------------------------------------------------------------
// Kernel 1: normalize -> [b][n][c]. FROZEN NUMERICS (R13 PASS).
// ---------------------------------------------------------------------------
__global__ void normalize_kernel(const float* __restrict__ x) {
    __shared__ float s[32][33];
    __shared__ float nrm[32];
    int b = blockIdx.y;
    int n0 = blockIdx.x * 32;
    int tx = threadIdx.x, ty = threadIdx.y;
    s[ty][tx] = x[(b * NC + ty) * NN + n0 + tx];
    __syncthreads();
    if (ty == 0) {
        float p0 = 0.f, p1 = 0.f, p2 = 0.f, p3 = 0.f;
#pragma unroll
        for (int i = 0; i < 8; i++) {
            float t0 = s[4 * i + 0][tx];
            float t1 = s[4 * i + 1][tx];
            float t2 = s[4 * i + 2][tx];
            float t3 = s[4 * i + 3][tx];
            p0 = __fadd_rn(p0, __fmul_rn(t0, t0));
            p1 = __fadd_rn(p1, __fmul_rn(t1, t1));
            p2 = __fadd_rn(p2, __fmul_rn(t2, t2));
            p3 = __fadd_rn(p3, __fmul_rn(t3, t3));
        }
        float ss = __fadd_rn(__fadd_rn(p0, p2), __fadd_rn(p1, p3));
        nrm[tx] = fmaxf(__fsqrt_rn(ss), 1e-12f);
    }
    __syncthreads();
    g_xnT[(b * NN + n0 + ty) * NC + tx] = div_full(s[tx][ty], nrm[ty]);
}

// ---------------------------------------------------------------------------
// Kernel 2: fused cosine-sim GEMM + top-9.
// 64 rows x 64-col tiles (3136 = 49*64, no OOB). 4 rows x 4 cols per thread
// (acc = 8 u64 = 16 regs live -> no spills at 3 blocks/SM). colS lives in
// buf cols [0,64); simS in buf cols [68,132) -> disjoint -> 2 barriers/tile,
// col LDGs overlap previous scan. Chains bit-identical to R13/R14.
// ---------------------------------------------------------------------------
__global__ __launch_bounds__(256, 3) void simtopk_kernel() {
    __shared__ __align__(16) float rowS[32 * 64];    // [c][r], 8.2 KB
    __shared__ __align__(16) float buf[64 * 132];    // colS [c][0..63] / simS [r][68..131] / merge

    int b = blockIdx.y;
    int r0 = blockIdx.x * 64;
    int tid = threadIdx.x;
    const float4* xnT4 = reinterpret_cast<const float4*>(g_xnT);

    // load 64 row vectors, transpose to c-major [c][r]
#pragma unroll
    for (int i = 0; i < 2; i++) {
        int l = tid + i * 256;
        int r = l >> 3, c4 = l & 7;
        float4 v = xnT4[(b * NN + r0 + r) * 8 + c4];
        rowS[(4 * c4 + 0) * 64 + r] = v.x;
        rowS[(4 * c4 + 1) * 64 + r] = v.y;
        rowS[(4 * c4 + 2) * 64 + r] = v.z;
        rowS[(4 * c4 + 3) * 64 + r] = v.w;
    }

    float vals[9];
    int idxs[9];
#pragma unroll
    for (int k = 0; k < 9; k++) { vals[k] = -3.f; idxs[k] = 0x7fffffff; }

    int rq = tid >> 4, tx = tid & 15;   // GEMM: rows rq*4..+3, cols tx*4..+3
    int srow = tid >> 2, g = tid & 3;   // scan: 4 threads per row
    int rglob = r0 + srow;

    for (int t = 0; t < 49; t++) {
        int mbase = t * 64;
        // load 64 col vectors into buf[c][m], m in [0,64) — overlaps scan(t-1)
#pragma unroll
        for (int i = 0; i < 2; i++) {
            int l = tid + i * 256;
            int m = l >> 3, c4 = l & 7;
            float4 v = xnT4[(b * NN + mbase + m) * 8 + c4];
            buf[(4 * c4 + 0) * 132 + m] = v.x;
            buf[(4 * c4 + 1) * 132 + m] = v.y;
            buf[(4 * c4 + 2) * 132 + m] = v.z;
            buf[(4 * c4 + 3) * 132 + m] = v.w;
        }
        __syncthreads();   // B: colS ready; scan(t-1) complete

        unsigned long long acc[4][2];
#pragma unroll
        for (int r = 0; r < 4; r++) { acc[r][0] = 0ull; acc[r][1] = 0ull; }

#pragma unroll
        for (int c = 0; c < 32; c++) {
            float4 rv = *reinterpret_cast<const float4*>(&rowS[c * 64 + rq * 4]);
            ulonglong2 cp = *reinterpret_cast<const ulonglong2*>(&buf[c * 132 + tx * 4]);
            unsigned long long rr0 = pack2(rv.x), rr1 = pack2(rv.y);
            unsigned long long rr2 = pack2(rv.z), rr3 = pack2(rv.w);
            acc[0][0] = ffma2(rr0, cp.x, acc[0][0]); acc[0][1] = ffma2(rr0, cp.y, acc[0][1]);
            acc[1][0] = ffma2(rr1, cp.x, acc[1][0]); acc[1][1] = ffma2(rr1, cp.y, acc[1][1]);
            acc[2][0] = ffma2(rr2, cp.x, acc[2][0]); acc[2][1] = ffma2(rr2, cp.y, acc[2][1]);
            acc[3][0] = ffma2(rr3, cp.x, acc[3][0]); acc[3][1] = ffma2(rr3, cp.y, acc[3][1]);
        }
        // write sim tile to buf[r][68+mm] (disjoint from colS region)
#pragma unroll
        for (int r = 0; r < 4; r++) {
            ulonglong2 q; q.x = acc[r][0]; q.y = acc[r][1];
            *reinterpret_cast<ulonglong2*>(&buf[(rq * 4 + r) * 132 + 68 + tx * 4]) = q;
        }
        __syncthreads();   // C: simS ready

        // scan: 4 threads per row, mm = g + 4j ascending (stable ties)
#pragma unroll
        for (int j = 0; j < 16; j++) {
            int mm = g + j * 4;
            int gm = mbase + mm;
            float v = buf[srow * 132 + 68 + mm];
            v = fminf(fmaxf(v, -1.f), 1.f);
            if (gm == rglob) v = 1.1f;   // self always best
            if (v > vals[8]) {
                float cv = v; int ci = gm;
#pragma unroll
                for (int s = 0; s < 9; s++) {
                    if (cv > vals[s]) {
                        float tv = vals[s]; int ti = idxs[s];
                        vals[s] = cv; idxs[s] = ci;
                        cv = tv; ci = ti;
                    }
                }
            }
        }
    }
    __syncthreads();

    // dump per-thread sorted top-9 (vals at buf[0..2303], idxs at int ofs 2304)
    int* bufI = reinterpret_cast<int*>(buf) + 2304;
    int base = tid * 9;   // (srow*4 + g) == tid
#pragma unroll
    for (int k = 0; k < 9; k++) { buf[base + k] = vals[k]; bufI[base + k] = idxs[k]; }
    __syncthreads();

    // merge 4 lists (36 entries) per row; one thread per row
    if (tid < 64) {
        float* mv = &buf[tid * 36];
        int*   mi = &bufI[tid * 36];
        int obase = (b * NN + r0 + tid) * 9;
        for (int k = 0; k < 9; k++) {
            float bv = -4.f; int bm = 0x7fffffff; int be = 0;
            for (int e = 0; e < 36; e++) {
                float v = mv[e];
                int m2 = mi[e];
                if (v > bv || (v == bv && m2 < bm)) { bv = v; bm = m2; be = e; }
            }
            mv[be] = -4.f;  // consume
            g_idx[obase + k] = bm;
        }
    }
}

// ---------------------------------------------------------------------------
// Kernel 3: dense GEMM  Y[b][k][m][o] = sum_c w[o][c][k] * x[b][c][m]
// ---------------------------------------------------------------------------
__global__ __launch_bounds__(256) void convA_kernel(const float* __restrict__ x,
                                                    const float* __restrict__ w) {
    __shared__ __align__(16) float wS[32 * 32];    // [c][o]
    __shared__ __align__(16) float xfS[32 * 132];  // [c][m]
    int mt = blockIdx.x, k = blockIdx.y, b = blockIdx.z;
    int mbase = mt * 128;
    int tid = threadIdx.x;

    for (int l = tid; l < 1024; l += 256) {
        int c = l >> 5, o = l & 31;
        wS[c * 32 + o] = w[o * (NC * NK) + c * NK + k];
    }
#pragma unroll
    for (int i = 0; i < 16; i++) {
        int l = tid + i * 256;
        int c = l >> 7, m = l & 127;
        int gm = mbase + m;
        xfS[c * 132 + m] = (gm < NN) ? x[(b * NC + c) * NN + gm] : 0.f;
    }
    __syncthreads();

    int ty = tid >> 5, tx = tid & 31;   // o-quad ty*4, m-quad tx*4
    float4 acc0 = {0, 0, 0, 0}, acc1 = {0, 0, 0, 0};
    float4 acc2 = {0, 0, 0, 0}, acc3 = {0, 0, 0, 0};
#pragma unroll
    for (int c = 0; c < 32; c++) {
        float4 of = *reinterpret_cast<const float4*>(&wS[c * 32 + ty * 4]);
        float4 mf = *reinterpret_cast<const float4*>(&xfS[c * 132 + tx * 4]);
        acc0.x = __fmaf_rn(of.x, mf.x, acc0.x); acc0.y = __fmaf_rn(of.y, mf.x, acc0.y);
        acc0.z = __fmaf_rn(of.z, mf.x, acc0.z); acc0.w = __fmaf_rn(of.w, mf.x, acc0.w);
        acc1.x = __fmaf_rn(of.x, mf.y, acc1.x); acc1.y = __fmaf_rn(of.y, mf.y, acc1.y);
        acc1.z = __fmaf_rn(of.z, mf.y, acc1.z); acc1.w = __fmaf_rn(of.w, mf.y, acc1.w);
        acc2.x = __fmaf_rn(of.x, mf.z, acc2.x); acc2.y = __fmaf_rn(of.y, mf.z, acc2.y);
        acc2.z = __fmaf_rn(of.z, mf.z, acc2.z); acc2.w = __fmaf_rn(of.w, mf.z, acc2.w);
        acc3.x = __fmaf_rn(of.x, mf.w, acc3.x); acc3.y = __fmaf_rn(of.y, mf.w, acc3.y);
        acc3.z = __fmaf_rn(of.z, mf.w, acc3.z); acc3.w = __fmaf_rn(of.w, mf.w, acc3.w);
    }
    int ybase = (b * NK + k) * NN;
    float4 acc[4] = {acc0, acc1, acc2, acc3};
#pragma unroll
    for (int j = 0; j < 4; j++) {
        int gm = mbase + tx * 4 + j;
        if (gm < NN)
            *reinterpret_cast<float4*>(&g_Y[(ybase + gm) * 32 + ty * 4]) = acc[j];
    }
}

// ---------------------------------------------------------------------------
// Kernel 4: gather-sum  out[b][o][n] = bias[o] + sum_k Y[b][k][idx[n][k]][o]
// ---------------------------------------------------------------------------
__global__ __launch_bounds__(256) void gather_kernel(const float* __restrict__ bias,
                                                     float* __restrict__ out) {
    int tid = threadIdx.x;
    int lane = tid & 31;
    int wg = blockIdx.x * 8 + (tid >> 5);   // one warp per (b, n)
    int b = wg / NN, n = wg - b * NN;
    int myidx = 0;
    if (lane < NK) myidx = g_idx[(b * NN + n) * NK + lane];
    float acc = bias[lane];
#pragma unroll
    for (int k = 0; k < NK; k++) {
        int m = __shfl_sync(0xffffffffu, myidx, k);
        acc += g_Y[((b * NK + k) * NN + m) * 32 + lane];  // 128B coalesced
    }
    out[(b * NC + lane) * NN + n] = acc;
}

// ---------------------------------------------------------------------------
extern "C" void kernel_launch(void* const* d_in, const int* in_sizes, int n_in,
                              void* d_out, int out_size) {
    const float* x    = (const float*)d_in[0];
    const float* w    = (const float*)d_in[1];
    const float* bias = (const float*)d_in[2];
    float* out = (float*)d_out;
    (void)in_sizes; (void)n_in; (void)out_size;

    normalize_kernel<<<dim3(NN / 32, NB), dim3(32, 32)>>>(x);
    simtopk_kernel<<<dim3(NN / 64, NB), 256>>>();
    convA_kernel<<<dim3(25, NK, NB), 256>>>(x, w);
    gather_kernel<<<NB * NN / 8, 256>>>(bias, out);
}